// round 11
// baseline (speedup 1.0000x reference)
#include <cuda_runtime.h>
#include <cuda_fp16.h>
#include <cstdint>

#define N_NODES 100000
#define N_EDGES 1600000
#define NFEAT   128
#define NHID    64
#define NCLASS  16
#define NBLK_SC 400          // scan blocks: 400*256 = 102400 >= N_NODES

// Scratch (device globals — no allocation allowed in kernel_launch)
__device__ __half g_h1h[N_NODES * NHID];    // X @ W1 (fp16, gathered by agg)
__device__ float  g_h2[N_NODES * NCLASS];   // layer-2 features (fp32)
__device__ int    g_hist[N_NODES];          // in-degree histogram (zeroed by scan_final each run)
__device__ int    g_off[N_NODES];           // CSR bin start
__device__ int    g_cur[N_NODES];           // permute cursor (== bin end after permute)
__device__ int    g_bsum[NBLK_SC];          // scan block partials
__device__ uint2  g_sorted[N_EDGES];        // {src, weight} bucketed by dst

// ---------------- f32x2 packed helpers (SASS FFMA2 — only via PTX) ----------
__device__ __forceinline__ void fma2(unsigned long long& d,
                                     unsigned long long a,
                                     unsigned long long b) {
    asm("fma.rn.f32x2 %0, %1, %2, %3;" : "=l"(d) : "l"(a), "l"(b), "l"(d));
}
__device__ __forceinline__ unsigned long long add2(unsigned long long a,
                                                   unsigned long long b) {
    unsigned long long r;
    asm("add.rn.f32x2 %0, %1, %2;" : "=l"(r) : "l"(a), "l"(b));
    return r;
}
__device__ __forceinline__ unsigned long long pack2(float a) {
    unsigned long long r;
    asm("mov.b64 %0, {%1, %1};" : "=l"(r) : "f"(a));
    return r;
}
__device__ __forceinline__ unsigned long long packf2(float2 f) {
    unsigned long long r;
    asm("mov.b64 %0, {%1, %2};" : "=l"(r) : "f"(f.x), "f"(f.y));
    return r;
}
__device__ __forceinline__ float2 unpack2(unsigned long long p) {
    float2 f;
    asm("mov.b64 {%0, %1}, %2;" : "=f"(f.x), "=f"(f.y) : "l"(p));
    return f;
}
__device__ __forceinline__ uint32_t f2tf32(float f) {
    uint32_t r;
    asm("cvt.rna.tf32.f32 %0, %1;" : "=r"(r) : "f"(f));
    return r;
}

// ---------------------------------------------------------------------------
// hist: in-degree of graph 1. g_hist starts zeroed (BSS at init; restored to
// zero by scan_final at the end of every run — self-cleaning across replays).
// ---------------------------------------------------------------------------
__global__ __launch_bounds__(256) void hist_kernel(const int* __restrict__ ei) {
    int e = blockIdx.x * blockDim.x + threadIdx.x;
    if (e < N_EDGES) atomicAdd(&g_hist[ei[N_EDGES + e]], 1);
}

// ---------------------------------------------------------------------------
// scan_partial: per-block sums of g_hist -> g_bsum.
// ---------------------------------------------------------------------------
__global__ __launch_bounds__(256) void scan_partial_kernel() {
    __shared__ int ws[8];
    const int t = threadIdx.x;
    int idx = blockIdx.x * 256 + t;
    int v = (idx < N_NODES) ? g_hist[idx] : 0;
    int s = v;
#pragma unroll
    for (int m = 16; m; m >>= 1) s += __shfl_xor_sync(0xffffffffu, s, m);
    if ((t & 31) == 0) ws[t >> 5] = s;
    __syncthreads();
    if (t == 0) {
        int tot = 0;
#pragma unroll
        for (int i = 0; i < 8; i++) tot += ws[i];
        g_bsum[blockIdx.x] = tot;
    }
}

// ---------------------------------------------------------------------------
// scan_final: block base = reduce(g_bsum[0..b)), local exclusive scan,
// writes g_off/g_cur, RESTORES g_hist to 0, and zeroes d_out in its tail.
// ---------------------------------------------------------------------------
__global__ __launch_bounds__(256) void scan_final_kernel(float* __restrict__ out) {
    __shared__ int ts[256];
    __shared__ int red[8];
    const int t = threadIdx.x;
    const int b = blockIdx.x;

    // base = sum of g_bsum[i] for i < b
    int part = 0;
    for (int i = t; i < b; i += 256) part += g_bsum[i];
#pragma unroll
    for (int m = 16; m; m >>= 1) part += __shfl_xor_sync(0xffffffffu, part, m);
    if ((t & 31) == 0) red[t >> 5] = part;
    __syncthreads();
    int base = red[0] + red[1] + red[2] + red[3] + red[4] + red[5] + red[6] + red[7];

    int idx = b * 256 + t;
    int v = (idx < N_NODES) ? g_hist[idx] : 0;
    ts[t] = v;
    __syncthreads();
    for (int off = 1; off < 256; off <<= 1) {
        int u = (t >= off) ? ts[t - off] : 0;
        __syncthreads();
        ts[t] += u;
        __syncthreads();
    }
    if (idx < N_NODES) {
        int o = base + ts[t] - v;      // exclusive
        g_off[idx] = o;
        g_cur[idx] = o;
        g_hist[idx] = 0;               // restore for next run
    }

    // zero d_out: 400K float4, 102400 threads -> 4 each
    const float4 z = make_float4(0.f, 0.f, 0.f, 0.f);
    const int n4 = N_NODES * NCLASS / 4;
    for (int i = b * 256 + t; i < n4; i += NBLK_SC * 256)
        reinterpret_cast<float4*>(out)[i] = z;
}

// ---------------------------------------------------------------------------
// permute: bucket edges by dst. g_cur[d] ends at bin end. (Profiled @ idx 3.)
// ---------------------------------------------------------------------------
__global__ __launch_bounds__(256) void permute_kernel(const int* __restrict__ ei,
                                                      const float* __restrict__ ew) {
    int e = blockIdx.x * blockDim.x + threadIdx.x;
    if (e >= N_EDGES) return;
    int s = ei[e];
    int d = ei[N_EDGES + e];
    float w = ew[e];
    int pos = atomicAdd(&g_cur[d], 1);
    g_sorted[pos] = make_uint2((unsigned)s, __float_as_uint(w));
}

// ---------------------------------------------------------------------------
// GEMM1 (tf32 tensor cores): h1 = X[100000,128] @ W1[128,64], fp16 output.
// ---------------------------------------------------------------------------
__global__ __launch_bounds__(256) void gemm1_kernel(const float* __restrict__ X,
                                                    const float* __restrict__ W) {
    __shared__ float Xs[128][36];
    __shared__ float Ws[32][72];

    const int tid  = threadIdx.x;
    const int lane = tid & 31;
    const int warp = tid >> 5;
    const int m0   = blockIdx.x * 128;
    const int wm   = warp >> 1;
    const int wn   = warp & 1;
    const int gr   = lane >> 2;
    const int tg   = lane & 3;

    float acc[2][4][4];
#pragma unroll
    for (int mi = 0; mi < 2; mi++)
#pragma unroll
        for (int ni = 0; ni < 4; ni++)
#pragma unroll
            for (int r = 0; r < 4; r++) acc[mi][ni][r] = 0.f;

    for (int kc = 0; kc < NFEAT; kc += 32) {
        __syncthreads();
#pragma unroll
        for (int t = 0; t < 4; t++) {
            int f4  = tid + t * 256;
            int row = f4 >> 3;
            int c4  = (f4 & 7) * 4;
            int gm  = m0 + row;
            float4 v = make_float4(0.f, 0.f, 0.f, 0.f);
            if (gm < N_NODES)
                v = *reinterpret_cast<const float4*>(&X[gm * NFEAT + kc + c4]);
            Xs[row][c4 + 0] = __uint_as_float(f2tf32(v.x));
            Xs[row][c4 + 1] = __uint_as_float(f2tf32(v.y));
            Xs[row][c4 + 2] = __uint_as_float(f2tf32(v.z));
            Xs[row][c4 + 3] = __uint_as_float(f2tf32(v.w));
        }
#pragma unroll
        for (int t = 0; t < 2; t++) {
            int f4  = tid + t * 256;
            int row = f4 >> 4;
            int c4  = (f4 & 15) * 4;
            float4 v = *reinterpret_cast<const float4*>(&W[(kc + row) * NHID + c4]);
            Ws[row][c4 + 0] = __uint_as_float(f2tf32(v.x));
            Ws[row][c4 + 1] = __uint_as_float(f2tf32(v.y));
            Ws[row][c4 + 2] = __uint_as_float(f2tf32(v.z));
            Ws[row][c4 + 3] = __uint_as_float(f2tf32(v.w));
        }
        __syncthreads();

#pragma unroll
        for (int ks = 0; ks < 32; ks += 8) {
            uint32_t a[2][4];
#pragma unroll
            for (int mi = 0; mi < 2; mi++) {
                int base = wm * 32 + mi * 16;
                a[mi][0] = __float_as_uint(Xs[base + gr][ks + tg]);
                a[mi][1] = __float_as_uint(Xs[base + gr + 8][ks + tg]);
                a[mi][2] = __float_as_uint(Xs[base + gr][ks + tg + 4]);
                a[mi][3] = __float_as_uint(Xs[base + gr + 8][ks + tg + 4]);
            }
#pragma unroll
            for (int ni = 0; ni < 4; ni++) {
                int cb = wn * 32 + ni * 8;
                uint32_t b0 = __float_as_uint(Ws[ks + tg][cb + gr]);
                uint32_t b1 = __float_as_uint(Ws[ks + tg + 4][cb + gr]);
#pragma unroll
                for (int mi = 0; mi < 2; mi++) {
                    asm volatile(
                        "mma.sync.aligned.m16n8k8.row.col.f32.tf32.tf32.f32 "
                        "{%0,%1,%2,%3}, {%4,%5,%6,%7}, {%8,%9}, {%0,%1,%2,%3};"
                        : "+f"(acc[mi][ni][0]), "+f"(acc[mi][ni][1]),
                          "+f"(acc[mi][ni][2]), "+f"(acc[mi][ni][3])
                        : "r"(a[mi][0]), "r"(a[mi][1]), "r"(a[mi][2]), "r"(a[mi][3]),
                          "r"(b0), "r"(b1));
                }
            }
        }
    }

#pragma unroll
    for (int mi = 0; mi < 2; mi++) {
#pragma unroll
        for (int ni = 0; ni < 4; ni++) {
            int row = m0 + wm * 32 + mi * 16 + gr;
            int col = wn * 32 + ni * 8 + tg * 2;
            if (row < N_NODES)
                *reinterpret_cast<__half2*>(&g_h1h[row * NHID + col]) =
                    __floats2half2_rn(acc[mi][ni][0], acc[mi][ni][1]);
            if (row + 8 < N_NODES)
                *reinterpret_cast<__half2*>(&g_h1h[(row + 8) * NHID + col]) =
                    __floats2half2_rn(acc[mi][ni][2], acc[mi][ni][3]);
        }
    }
}

// ---------------------------------------------------------------------------
// Fused aggregate1 + ReLU + GEMM2: one warp per node, zero atomics.
// Bin walk pipelined x8: 8 independent g_sorted loads then 8 independent
// 128B coalesced fp16 row gathers (MLP 8). W2 staged TRANSPOSED Wt[c][k]
// (row stride 66) so the per-lane float2 at Wt[c][2*lane] is bank-conflict-
// free (the R6/R7 versions had 8/32-way conflicts here — the real bug).
// ---------------------------------------------------------------------------
__global__ __launch_bounds__(256) void agg_gemm2_kernel(const float* __restrict__ W2) {
    __shared__ float Wt[NCLASS][NHID + 2];   // transposed: Wt[c][k], stride 66
    const int tid = threadIdx.x;
    for (int i = tid; i < NHID * NCLASS; i += 256) {
        int k = i >> 4;          // 0..63
        int c = i & 15;          // 0..15
        Wt[c][k] = W2[i];        // W2 row-major [64][16]
    }
    __syncthreads();

    const int lane = tid & 31;
    const int node = blockIdx.x * 8 + (tid >> 5);
    if (node >= N_NODES) return;

    const int beg = g_off[node];
    const int end = g_cur[node];

    unsigned long long acc = 0;              // hid pair [2*lane, 2*lane+1] fp32
    const uint32_t* h1u = reinterpret_cast<const uint32_t*>(g_h1h);

    for (int e = beg; e < end; e += 8) {
        uint2 sw[8];
#pragma unroll
        for (int i = 0; i < 8; i++) {
            int idx = (e + i < end) ? (e + i) : beg;   // clamp (bin nonempty here)
            sw[i] = g_sorted[idx];
        }
#pragma unroll
        for (int i = 0; i < 8; i++)
            if (e + i >= end) sw[i].y = 0u;            // weight 0 for tail
        uint32_t r[8];
#pragma unroll
        for (int i = 0; i < 8; i++)
            r[i] = h1u[sw[i].x * 32 + lane];           // 8 independent 128B rows
#pragma unroll
        for (int i = 0; i < 8; i++)
            fma2(acc, packf2(__half22float2(*reinterpret_cast<__half2*>(&r[i]))),
                 pack2(__uint_as_float(sw[i].y)));
    }

    // ReLU
    float2 af = unpack2(acc);
    float a0 = fmaxf(af.x, 0.f);
    float a1 = fmaxf(af.y, 0.f);

    // W2 partials: lane covers k = 2*lane, 2*lane+1; conflict-free Wt reads
    unsigned long long oacc[8];
#pragma unroll
    for (int p = 0; p < 8; p++) {
        float2 wa = *reinterpret_cast<const float2*>(&Wt[2 * p][2 * lane]);
        float2 wb = *reinterpret_cast<const float2*>(&Wt[2 * p + 1][2 * lane]);
        float px = a0 * wa.x + a1 * wa.y;
        float py = a0 * wb.x + a1 * wb.y;
        oacc[p] = packf2(make_float2(px, py));
    }

    // butterfly reduce across 32 lanes
#pragma unroll
    for (int m = 1; m < 32; m <<= 1)
#pragma unroll
        for (int p = 0; p < 8; p++)
            oacc[p] = add2(oacc[p], __shfl_xor_sync(0xffffffffu, oacc[p], m));

    // lanes 0-7: lane j writes output cols [2j, 2j+2)
    if (lane < 8) {
        float2 o = unpack2(oacc[lane]);
        *reinterpret_cast<float2*>(&g_h2[node * NCLASS + 2 * lane]) =
            make_float2(o.x, o.y);
    }
}

// ---------------------------------------------------------------------------
// scatter2: out[dst] += w * h2[src].  4 threads/edge, float4 gather + red.v4.
// ---------------------------------------------------------------------------
__global__ __launch_bounds__(256) void scatter2_kernel(const int* __restrict__ ei,
                                                       const float* __restrict__ ew,
                                                       float* __restrict__ out) {
    int gid = blockIdx.x * blockDim.x + threadIdx.x;
    int e = gid >> 2;
    int c = gid & 3;
    if (e >= N_EDGES) return;
    int s = ei[e];
    int d = ei[N_EDGES + e];
    float w = ew[e];
    float4 v = *reinterpret_cast<const float4*>(&g_h2[s * NCLASS + c * 4]);
    float* dst = &out[d * NCLASS + c * 4];
    asm volatile("red.global.add.v4.f32 [%0], {%1, %2, %3, %4};"
                 :: "l"(dst), "f"(v.x * w), "f"(v.y * w), "f"(v.z * w), "f"(v.w * w)
                 : "memory");
}

// ---------------------------------------------------------------------------
extern "C" void kernel_launch(void* const* d_in, const int* in_sizes, int n_in,
                              void* d_out, int out_size) {
    const float* x   = (const float*)d_in[0];
    const int*   ei1 = (const int*)  d_in[1];
    const int*   ei2 = (const int*)  d_in[2];
    const float* ew1 = (const float*)d_in[3];
    const float* ew2 = (const float*)d_in[4];
    const float* W1  = (const float*)d_in[5];
    const float* W2  = (const float*)d_in[6];
    float* out = (float*)d_out;

    hist_kernel<<<(N_EDGES + 255) / 256, 256>>>(ei1);          // idx 0
    scan_partial_kernel<<<NBLK_SC, 256>>>();                   // idx 1
    scan_final_kernel<<<NBLK_SC, 256>>>(out);                  // idx 2 (+d_out zero)
    permute_kernel<<<(N_EDGES + 255) / 256, 256>>>(ei1, ew1);  // idx 3 (profiled)
    gemm1_kernel<<<(N_NODES + 127) / 128, 256>>>(x, W1);       // idx 4
    agg_gemm2_kernel<<<(N_NODES + 7) / 8, 256>>>(W2);          // idx 5
    scatter2_kernel<<<(N_EDGES * 4 + 255) / 256, 256>>>(ei2, ew2, out);  // idx 6
}

// round 12
// speedup vs baseline: 1.0232x; 1.0232x over previous
#include <cuda_runtime.h>
#include <cstdint>

#define N_NODES 100000
#define N_EDGES 1600000
#define NFEAT   128
#define NHID    64
#define NCLASS  16

// Scratch (device globals — no allocation allowed in kernel_launch)
__device__ float g_h1[N_NODES * NHID];     // X @ W1 (fp32)
__device__ float g_agg1[N_NODES * NHID];   // scatter1 accumulator
__device__ float g_h2[N_NODES * NCLASS];   // relu(agg1) @ W2

// ---------------- f32x2 packed helpers (SASS FFMA2 — only via PTX) ----------
__device__ __forceinline__ void fma2(unsigned long long& d,
                                     unsigned long long a,
                                     unsigned long long b) {
    asm("fma.rn.f32x2 %0, %1, %2, %3;" : "=l"(d) : "l"(a), "l"(b), "l"(d));
}
__device__ __forceinline__ unsigned long long pack2(float a) {
    unsigned long long r;
    asm("mov.b64 %0, {%1, %1};" : "=l"(r) : "f"(a));
    return r;
}
__device__ __forceinline__ float2 unpack2(unsigned long long p) {
    float2 f;
    asm("mov.b64 {%0, %1}, %2;" : "=f"(f.x), "=f"(f.y) : "l"(p));
    return f;
}
__device__ __forceinline__ uint32_t f2tf32(float f) {
    uint32_t r;
    asm("cvt.rna.tf32.f32 %0, %1;" : "=r"(r) : "f"(f));
    return r;
}

// ---------------------------------------------------------------------------
// zero_agg1 (launch 0) and zero_out (launch 1): split so scatter1 lands on
// launch index 3, which the profiler captures.
// ---------------------------------------------------------------------------
__global__ void zero_agg1_kernel() {
    const int stride = gridDim.x * blockDim.x;
    int i = blockIdx.x * blockDim.x + threadIdx.x;
    const float4 z = make_float4(0.f, 0.f, 0.f, 0.f);
    const int n1 = N_NODES * NHID / 4;
    for (int idx = i; idx < n1; idx += stride)
        reinterpret_cast<float4*>(g_agg1)[idx] = z;
}

__global__ void zero_out_kernel(float* __restrict__ out) {
    const int stride = gridDim.x * blockDim.x;
    int i = blockIdx.x * blockDim.x + threadIdx.x;
    const float4 z = make_float4(0.f, 0.f, 0.f, 0.f);
    const int n2 = N_NODES * NCLASS / 4;
    for (int idx = i; idx < n2; idx += stride)
        reinterpret_cast<float4*>(out)[idx] = z;
}

// ---------------------------------------------------------------------------
// GEMM1 (tf32 tensor cores): h1 = X[100000,128] @ W1[128,64], fp32 output.
// Block: 256 threads = 8 warps, tile 128(M) x 64(N), K chunks of 32.
// ---------------------------------------------------------------------------
__global__ __launch_bounds__(256) void gemm1_kernel(const float* __restrict__ X,
                                                    const float* __restrict__ W) {
    __shared__ float Xs[128][36];
    __shared__ float Ws[32][72];

    const int tid  = threadIdx.x;
    const int lane = tid & 31;
    const int warp = tid >> 5;
    const int m0   = blockIdx.x * 128;
    const int wm   = warp >> 1;
    const int wn   = warp & 1;
    const int gr   = lane >> 2;
    const int tg   = lane & 3;

    float acc[2][4][4];
#pragma unroll
    for (int mi = 0; mi < 2; mi++)
#pragma unroll
        for (int ni = 0; ni < 4; ni++)
#pragma unroll
            for (int r = 0; r < 4; r++) acc[mi][ni][r] = 0.f;

    for (int kc = 0; kc < NFEAT; kc += 32) {
        __syncthreads();
#pragma unroll
        for (int t = 0; t < 4; t++) {
            int f4  = tid + t * 256;
            int row = f4 >> 3;
            int c4  = (f4 & 7) * 4;
            int gm  = m0 + row;
            float4 v = make_float4(0.f, 0.f, 0.f, 0.f);
            if (gm < N_NODES)
                v = *reinterpret_cast<const float4*>(&X[gm * NFEAT + kc + c4]);
            Xs[row][c4 + 0] = __uint_as_float(f2tf32(v.x));
            Xs[row][c4 + 1] = __uint_as_float(f2tf32(v.y));
            Xs[row][c4 + 2] = __uint_as_float(f2tf32(v.z));
            Xs[row][c4 + 3] = __uint_as_float(f2tf32(v.w));
        }
#pragma unroll
        for (int t = 0; t < 2; t++) {
            int f4  = tid + t * 256;
            int row = f4 >> 4;
            int c4  = (f4 & 15) * 4;
            float4 v = *reinterpret_cast<const float4*>(&W[(kc + row) * NHID + c4]);
            Ws[row][c4 + 0] = __uint_as_float(f2tf32(v.x));
            Ws[row][c4 + 1] = __uint_as_float(f2tf32(v.y));
            Ws[row][c4 + 2] = __uint_as_float(f2tf32(v.z));
            Ws[row][c4 + 3] = __uint_as_float(f2tf32(v.w));
        }
        __syncthreads();

#pragma unroll
        for (int ks = 0; ks < 32; ks += 8) {
            uint32_t a[2][4];
#pragma unroll
            for (int mi = 0; mi < 2; mi++) {
                int base = wm * 32 + mi * 16;
                a[mi][0] = __float_as_uint(Xs[base + gr][ks + tg]);
                a[mi][1] = __float_as_uint(Xs[base + gr + 8][ks + tg]);
                a[mi][2] = __float_as_uint(Xs[base + gr][ks + tg + 4]);
                a[mi][3] = __float_as_uint(Xs[base + gr + 8][ks + tg + 4]);
            }
#pragma unroll
            for (int ni = 0; ni < 4; ni++) {
                int cb = wn * 32 + ni * 8;
                uint32_t b0 = __float_as_uint(Ws[ks + tg][cb + gr]);
                uint32_t b1 = __float_as_uint(Ws[ks + tg + 4][cb + gr]);
#pragma unroll
                for (int mi = 0; mi < 2; mi++) {
                    asm volatile(
                        "mma.sync.aligned.m16n8k8.row.col.f32.tf32.tf32.f32 "
                        "{%0,%1,%2,%3}, {%4,%5,%6,%7}, {%8,%9}, {%0,%1,%2,%3};"
                        : "+f"(acc[mi][ni][0]), "+f"(acc[mi][ni][1]),
                          "+f"(acc[mi][ni][2]), "+f"(acc[mi][ni][3])
                        : "r"(a[mi][0]), "r"(a[mi][1]), "r"(a[mi][2]), "r"(a[mi][3]),
                          "r"(b0), "r"(b1));
                }
            }
        }
    }

#pragma unroll
    for (int mi = 0; mi < 2; mi++) {
#pragma unroll
        for (int ni = 0; ni < 4; ni++) {
            int row = m0 + wm * 32 + mi * 16 + gr;
            int col = wn * 32 + ni * 8 + tg * 2;
            if (row < N_NODES)
                *reinterpret_cast<float2*>(&g_h1[row * NHID + col]) =
                    make_float2(acc[mi][ni][0], acc[mi][ni][1]);
            if (row + 8 < N_NODES)
                *reinterpret_cast<float2*>(&g_h1[(row + 8) * NHID + col]) =
                    make_float2(acc[mi][ni][2], acc[mi][ni][3]);
        }
    }
}

// ---------------------------------------------------------------------------
// scatter1 (launch idx 3 -> PROFILED): agg1[dst] += w * h1[src].
// 16 threads/edge, one float4 gather + one red.global.add.v4.f32 per thread.
// ---------------------------------------------------------------------------
__global__ __launch_bounds__(256) void scatter1_kernel(const int* __restrict__ ei,
                                                       const float* __restrict__ ew) {
    int gid = blockIdx.x * blockDim.x + threadIdx.x;
    int e = gid >> 4;
    int c = gid & 15;
    if (e >= N_EDGES) return;
    int s = ei[e];
    int d = ei[N_EDGES + e];
    float w = ew[e];
    float4 v = *reinterpret_cast<const float4*>(&g_h1[s * NHID + c * 4]);
    float* dst = &g_agg1[d * NHID + c * 4];
    asm volatile("red.global.add.v4.f32 [%0], {%1, %2, %3, %4};"
                 :: "l"(dst), "f"(v.x * w), "f"(v.y * w), "f"(v.z * w), "f"(v.w * w)
                 : "memory");
}

// ---------------------------------------------------------------------------
// GEMM2 (+fused ReLU): h2 = relu(agg1)[100000,64] @ W2[64,16], fp32 output.
// Column-split, 2 threads per node (measured 18.8 us): each reads the full
// 64-k row (pair threads broadcast-share it) and computes 8 of 16 outputs.
// ---------------------------------------------------------------------------
__global__ __launch_bounds__(256) void gemm2_kernel(const float* __restrict__ W2) {
    __shared__ float Ws[NHID * NCLASS];  // [64][16] row-major, 1024 floats
    const int tid = threadIdx.x;
    reinterpret_cast<float4*>(Ws)[tid] = reinterpret_cast<const float4*>(W2)[tid];
    __syncthreads();

    int gid  = blockIdx.x * blockDim.x + tid;
    int node = gid >> 1;
    int half = gid & 1;                  // output cols [half*8, half*8+8)
    if (node >= N_NODES) return;

    unsigned long long acc[4] = {};      // 8 output cols as 4 f32x2 pairs

#pragma unroll
    for (int k4 = 0; k4 < NHID / 4; k4++) {
        float4 a = *reinterpret_cast<const float4*>(&g_agg1[node * NHID + k4 * 4]);
        a.x = fmaxf(a.x, 0.f); a.y = fmaxf(a.y, 0.f);
        a.z = fmaxf(a.z, 0.f); a.w = fmaxf(a.w, 0.f);
#pragma unroll
        for (int j = 0; j < 4; j++) {
            float av = (j == 0) ? a.x : (j == 1) ? a.y : (j == 2) ? a.z : a.w;
            unsigned long long ap = pack2(av);
            const ulonglong2* wr = reinterpret_cast<const ulonglong2*>(
                &Ws[(k4 * 4 + j) * NCLASS + half * 8]);
            ulonglong2 wa = wr[0];
            ulonglong2 wb = wr[1];
            fma2(acc[0], ap, wa.x); fma2(acc[1], ap, wa.y);
            fma2(acc[2], ap, wb.x); fma2(acc[3], ap, wb.y);
        }
    }

#pragma unroll
    for (int p = 0; p < 2; p++) {
        float2 lo = unpack2(acc[p * 2 + 0]);
        float2 hi = unpack2(acc[p * 2 + 1]);
        *reinterpret_cast<float4*>(&g_h2[node * NCLASS + half * 8 + p * 4]) =
            make_float4(lo.x, lo.y, hi.x, hi.y);
    }
}

// ---------------------------------------------------------------------------
// scatter2: out[dst] += w * h2[src].  4 threads/edge, float4 gather + red.v4.
// ---------------------------------------------------------------------------
__global__ __launch_bounds__(256) void scatter2_kernel(const int* __restrict__ ei,
                                                       const float* __restrict__ ew,
                                                       float* __restrict__ out) {
    int gid = blockIdx.x * blockDim.x + threadIdx.x;
    int e = gid >> 2;
    int c = gid & 3;
    if (e >= N_EDGES) return;
    int s = ei[e];
    int d = ei[N_EDGES + e];
    float w = ew[e];
    float4 v = *reinterpret_cast<const float4*>(&g_h2[s * NCLASS + c * 4]);
    float* dst = &out[d * NCLASS + c * 4];
    asm volatile("red.global.add.v4.f32 [%0], {%1, %2, %3, %4};"
                 :: "l"(dst), "f"(v.x * w), "f"(v.y * w), "f"(v.z * w), "f"(v.w * w)
                 : "memory");
}

// ---------------------------------------------------------------------------
extern "C" void kernel_launch(void* const* d_in, const int* in_sizes, int n_in,
                              void* d_out, int out_size) {
    const float* x   = (const float*)d_in[0];
    const int*   ei1 = (const int*)  d_in[1];
    const int*   ei2 = (const int*)  d_in[2];
    const float* ew1 = (const float*)d_in[3];
    const float* ew2 = (const float*)d_in[4];
    const float* W1  = (const float*)d_in[5];
    const float* W2  = (const float*)d_in[6];
    float* out = (float*)d_out;

    zero_agg1_kernel<<<2048, 256>>>();                                    // idx 0
    zero_out_kernel<<<512, 256>>>(out);                                   // idx 1
    gemm1_kernel<<<(N_NODES + 127) / 128, 256>>>(x, W1);                  // idx 2
    scatter1_kernel<<<(N_EDGES * 16 + 255) / 256, 256>>>(ei1, ew1);       // idx 3 (profiled)
    gemm2_kernel<<<(N_NODES * 2 + 255) / 256, 256>>>(W2);                 // idx 4
    scatter2_kernel<<<(N_EDGES * 4 + 255) / 256, 256>>>(ei2, ew2, out);   // idx 5
}

// round 13
// speedup vs baseline: 1.0912x; 1.0664x over previous
#include <cuda_runtime.h>
#include <cstdint>

#define N_NODES 100000
#define N_EDGES 1600000
#define NFEAT   128
#define NHID    64
#define NCLASS  16

// Scratch (device globals — no allocation allowed in kernel_launch)
__device__ float g_h1[N_NODES * NHID];     // X @ W1 (fp32)
__device__ float g_agg1[N_NODES * NHID];   // scatter1 accumulator
__device__ float g_h2[N_NODES * NCLASS];   // relu(agg1) @ W2

__device__ __forceinline__ uint32_t f2tf32(float f) {
    uint32_t r;
    asm("cvt.rna.tf32.f32 %0, %1;" : "=r"(r) : "f"(f));
    return r;
}

// ---------------------------------------------------------------------------
// Zero agg1 and d_out (atomically accumulated; must start at 0 every launch).
// ---------------------------------------------------------------------------
__global__ void zero_kernel(float* __restrict__ out) {
    const int stride = gridDim.x * blockDim.x;
    int i = blockIdx.x * blockDim.x + threadIdx.x;
    const float4 z = make_float4(0.f, 0.f, 0.f, 0.f);
    const int n1 = N_NODES * NHID / 4;
    const int n2 = N_NODES * NCLASS / 4;
    for (int idx = i; idx < n1; idx += stride)
        reinterpret_cast<float4*>(g_agg1)[idx] = z;
    for (int idx = i; idx < n2; idx += stride)
        reinterpret_cast<float4*>(out)[idx] = z;
}

// ---------------------------------------------------------------------------
// GEMM1 (tf32 tensor cores): h1 = X[100000,128] @ W1[128,64], fp32 output.
// Block: 256 threads = 8 warps, tile 128(M) x 64(N), K chunks of 32.
// ---------------------------------------------------------------------------
__global__ __launch_bounds__(256) void gemm1_kernel(const float* __restrict__ X,
                                                    const float* __restrict__ W) {
    __shared__ float Xs[128][36];
    __shared__ float Ws[32][72];

    const int tid  = threadIdx.x;
    const int lane = tid & 31;
    const int warp = tid >> 5;
    const int m0   = blockIdx.x * 128;
    const int wm   = warp >> 1;
    const int wn   = warp & 1;
    const int gr   = lane >> 2;
    const int tg   = lane & 3;

    float acc[2][4][4];
#pragma unroll
    for (int mi = 0; mi < 2; mi++)
#pragma unroll
        for (int ni = 0; ni < 4; ni++)
#pragma unroll
            for (int r = 0; r < 4; r++) acc[mi][ni][r] = 0.f;

    for (int kc = 0; kc < NFEAT; kc += 32) {
        __syncthreads();
#pragma unroll
        for (int t = 0; t < 4; t++) {
            int f4  = tid + t * 256;
            int row = f4 >> 3;
            int c4  = (f4 & 7) * 4;
            int gm  = m0 + row;
            float4 v = make_float4(0.f, 0.f, 0.f, 0.f);
            if (gm < N_NODES)
                v = *reinterpret_cast<const float4*>(&X[gm * NFEAT + kc + c4]);
            Xs[row][c4 + 0] = __uint_as_float(f2tf32(v.x));
            Xs[row][c4 + 1] = __uint_as_float(f2tf32(v.y));
            Xs[row][c4 + 2] = __uint_as_float(f2tf32(v.z));
            Xs[row][c4 + 3] = __uint_as_float(f2tf32(v.w));
        }
#pragma unroll
        for (int t = 0; t < 2; t++) {
            int f4  = tid + t * 256;
            int row = f4 >> 4;
            int c4  = (f4 & 15) * 4;
            float4 v = *reinterpret_cast<const float4*>(&W[(kc + row) * NHID + c4]);
            Ws[row][c4 + 0] = __uint_as_float(f2tf32(v.x));
            Ws[row][c4 + 1] = __uint_as_float(f2tf32(v.y));
            Ws[row][c4 + 2] = __uint_as_float(f2tf32(v.z));
            Ws[row][c4 + 3] = __uint_as_float(f2tf32(v.w));
        }
        __syncthreads();

#pragma unroll
        for (int ks = 0; ks < 32; ks += 8) {
            uint32_t a[2][4];
#pragma unroll
            for (int mi = 0; mi < 2; mi++) {
                int base = wm * 32 + mi * 16;
                a[mi][0] = __float_as_uint(Xs[base + gr][ks + tg]);
                a[mi][1] = __float_as_uint(Xs[base + gr + 8][ks + tg]);
                a[mi][2] = __float_as_uint(Xs[base + gr][ks + tg + 4]);
                a[mi][3] = __float_as_uint(Xs[base + gr + 8][ks + tg + 4]);
            }
#pragma unroll
            for (int ni = 0; ni < 4; ni++) {
                int cb = wn * 32 + ni * 8;
                uint32_t b0 = __float_as_uint(Ws[ks + tg][cb + gr]);
                uint32_t b1 = __float_as_uint(Ws[ks + tg + 4][cb + gr]);
#pragma unroll
                for (int mi = 0; mi < 2; mi++) {
                    asm volatile(
                        "mma.sync.aligned.m16n8k8.row.col.f32.tf32.tf32.f32 "
                        "{%0,%1,%2,%3}, {%4,%5,%6,%7}, {%8,%9}, {%0,%1,%2,%3};"
                        : "+f"(acc[mi][ni][0]), "+f"(acc[mi][ni][1]),
                          "+f"(acc[mi][ni][2]), "+f"(acc[mi][ni][3])
                        : "r"(a[mi][0]), "r"(a[mi][1]), "r"(a[mi][2]), "r"(a[mi][3]),
                          "r"(b0), "r"(b1));
                }
            }
        }
    }

#pragma unroll
    for (int mi = 0; mi < 2; mi++) {
#pragma unroll
        for (int ni = 0; ni < 4; ni++) {
            int row = m0 + wm * 32 + mi * 16 + gr;
            int col = wn * 32 + ni * 8 + tg * 2;
            if (row < N_NODES)
                *reinterpret_cast<float2*>(&g_h1[row * NHID + col]) =
                    make_float2(acc[mi][ni][0], acc[mi][ni][1]);
            if (row + 8 < N_NODES)
                *reinterpret_cast<float2*>(&g_h1[(row + 8) * NHID + col]) =
                    make_float2(acc[mi][ni][2], acc[mi][ni][3]);
        }
    }
}

// ---------------------------------------------------------------------------
// scatter1: agg1[dst] += w * h1[src].  16 threads/edge, one float4 gather +
// one red.global.add.v4.f32 per thread (measured-best layout, 93.4 us —
// near the L2 read+atomic floor).
// ---------------------------------------------------------------------------
__global__ __launch_bounds__(256) void scatter1_kernel(const int* __restrict__ ei,
                                                       const float* __restrict__ ew) {
    int gid = blockIdx.x * blockDim.x + threadIdx.x;
    int e = gid >> 4;
    int c = gid & 15;
    if (e >= N_EDGES) return;
    int s = ei[e];
    int d = ei[N_EDGES + e];
    float w = ew[e];
    float4 v = *reinterpret_cast<const float4*>(&g_h1[s * NHID + c * 4]);
    float* dst = &g_agg1[d * NHID + c * 4];
    asm volatile("red.global.add.v4.f32 [%0], {%1, %2, %3, %4};"
                 :: "l"(dst), "f"(v.x * w), "f"(v.y * w), "f"(v.z * w), "f"(v.w * w)
                 : "memory");
}

// ---------------------------------------------------------------------------
// GEMM2 (tf32 tensor cores, fused ReLU): h2 = relu(agg1)[100000,64] @ W2[64,16].
// Block: 256 threads = 8 warps, tile 128(M) x 16(N), K = 64 in one smem stage.
// ReLU + tf32 conversion applied while staging agg1. Each warp owns 16 rows,
// 2 n8-groups, 8 k-steps of m16n8k8. Conflict-free frag strides (68 / 24).
// ---------------------------------------------------------------------------
__global__ __launch_bounds__(256) void gemm2_kernel(const float* __restrict__ W2) {
    __shared__ float As[128][68];    // relu(agg1) tile, tf32-rounded (34 KB)
    __shared__ float Bs[64][24];     // W2, tf32-rounded (6 KB)

    const int tid  = threadIdx.x;
    const int lane = tid & 31;
    const int warp = tid >> 5;
    const int m0   = blockIdx.x * 128;
    const int gr   = lane >> 2;
    const int tg   = lane & 3;

    // stage B: 64x16 = 1024 floats, 4 per thread
#pragma unroll
    for (int t = 0; t < 4; t++) {
        int i = tid + t * 256;
        int k = i >> 4;
        int c = i & 15;
        Bs[k][c] = __uint_as_float(f2tf32(W2[i]));
    }
    // stage A: 128 rows x 64 cols = 2048 float4, 8 per thread; relu fused
#pragma unroll
    for (int t = 0; t < 8; t++) {
        int f4  = tid + t * 256;
        int row = f4 >> 4;
        int c4  = (f4 & 15) * 4;
        int gm  = m0 + row;
        float4 v = make_float4(0.f, 0.f, 0.f, 0.f);
        if (gm < N_NODES)
            v = *reinterpret_cast<const float4*>(&g_agg1[gm * NHID + c4]);
        As[row][c4 + 0] = __uint_as_float(f2tf32(fmaxf(v.x, 0.f)));
        As[row][c4 + 1] = __uint_as_float(f2tf32(fmaxf(v.y, 0.f)));
        As[row][c4 + 2] = __uint_as_float(f2tf32(fmaxf(v.z, 0.f)));
        As[row][c4 + 3] = __uint_as_float(f2tf32(fmaxf(v.w, 0.f)));
    }
    __syncthreads();

    float acc[2][4];
#pragma unroll
    for (int ni = 0; ni < 2; ni++)
#pragma unroll
        for (int r = 0; r < 4; r++) acc[ni][r] = 0.f;

    const int rbase = warp * 16;
#pragma unroll
    for (int ks = 0; ks < NHID; ks += 8) {
        uint32_t a0 = __float_as_uint(As[rbase + gr][ks + tg]);
        uint32_t a1 = __float_as_uint(As[rbase + gr + 8][ks + tg]);
        uint32_t a2 = __float_as_uint(As[rbase + gr][ks + tg + 4]);
        uint32_t a3 = __float_as_uint(As[rbase + gr + 8][ks + tg + 4]);
#pragma unroll
        for (int ni = 0; ni < 2; ni++) {
            uint32_t b0 = __float_as_uint(Bs[ks + tg][ni * 8 + gr]);
            uint32_t b1 = __float_as_uint(Bs[ks + tg + 4][ni * 8 + gr]);
            asm volatile(
                "mma.sync.aligned.m16n8k8.row.col.f32.tf32.tf32.f32 "
                "{%0,%1,%2,%3}, {%4,%5,%6,%7}, {%8,%9}, {%0,%1,%2,%3};"
                : "+f"(acc[ni][0]), "+f"(acc[ni][1]),
                  "+f"(acc[ni][2]), "+f"(acc[ni][3])
                : "r"(a0), "r"(a1), "r"(a2), "r"(a3), "r"(b0), "r"(b1));
        }
    }

#pragma unroll
    for (int ni = 0; ni < 2; ni++) {
        int row = m0 + rbase + gr;
        int col = ni * 8 + tg * 2;
        if (row < N_NODES)
            *reinterpret_cast<float2*>(&g_h2[row * NCLASS + col]) =
                make_float2(acc[ni][0], acc[ni][1]);
        if (row + 8 < N_NODES)
            *reinterpret_cast<float2*>(&g_h2[(row + 8) * NCLASS + col]) =
                make_float2(acc[ni][2], acc[ni][3]);
    }
}

// ---------------------------------------------------------------------------
// scatter2: out[dst] += w * h2[src].  4 threads/edge, float4 gather + red.v4.
// ---------------------------------------------------------------------------
__global__ __launch_bounds__(256) void scatter2_kernel(const int* __restrict__ ei,
                                                       const float* __restrict__ ew,
                                                       float* __restrict__ out) {
    int gid = blockIdx.x * blockDim.x + threadIdx.x;
    int e = gid >> 2;
    int c = gid & 3;
    if (e >= N_EDGES) return;
    int s = ei[e];
    int d = ei[N_EDGES + e];
    float w = ew[e];
    float4 v = *reinterpret_cast<const float4*>(&g_h2[s * NCLASS + c * 4]);
    float* dst = &out[d * NCLASS + c * 4];
    asm volatile("red.global.add.v4.f32 [%0], {%1, %2, %3, %4};"
                 :: "l"(dst), "f"(v.x * w), "f"(v.y * w), "f"(v.z * w), "f"(v.w * w)
                 : "memory");
}

// ---------------------------------------------------------------------------
extern "C" void kernel_launch(void* const* d_in, const int* in_sizes, int n_in,
                              void* d_out, int out_size) {
    const float* x   = (const float*)d_in[0];
    const int*   ei1 = (const int*)  d_in[1];
    const int*   ei2 = (const int*)  d_in[2];
    const float* ew1 = (const float*)d_in[3];
    const float* ew2 = (const float*)d_in[4];
    const float* W1  = (const float*)d_in[5];
    const float* W2  = (const float*)d_in[6];
    float* out = (float*)d_out;

    zero_kernel<<<2048, 256>>>(out);                                      // idx 0
    gemm1_kernel<<<(N_NODES + 127) / 128, 256>>>(x, W1);                  // idx 1
    scatter1_kernel<<<(N_EDGES * 16 + 255) / 256, 256>>>(ei1, ew1);       // idx 2
    gemm2_kernel<<<(N_NODES + 127) / 128, 256>>>(W2);                     // idx 3 (profiled)
    scatter2_kernel<<<(N_EDGES * 4 + 255) / 256, 256>>>(ei2, ew2, out);   // idx 4
}